// round 9
// baseline (speedup 1.0000x reference)
#include <cuda_runtime.h>
#include <cstdint>

// Problem constants (fixed by the reference)
#define Bn       8
#define Nn       32768
#define CINn     128
#define Mn       (Nn / 4)          // 8192 sampled points
#define CLUSTER  8                 // CTAs per batch (one cluster)
#define PTS_CTA  (Nn / CLUSTER)    // 4096 points per CTA
#define THREADS  512
#define PTS_THR  (PTS_CTA / THREADS) // 8 points per thread
#define NWARPS   (THREADS / 32)

// Scratch: selected indices per batch (allowed: __device__ global, no alloc)
__device__ int g_idx[Bn * Mn];

__device__ __forceinline__ uint32_t smem_u32(const void* p) {
    return (uint32_t)__cvta_generic_to_shared(p);
}

__device__ __forceinline__ unsigned long long u64max(unsigned long long a,
                                                     unsigned long long b) {
    return a > b ? a : b;
}

// ---------------------------------------------------------------------------
// FPS kernel: one cluster of 8 CTAs per batch. xyz slice + running distance
// live entirely in registers. Per-iteration cross-CTA argmax via DSMEM slot
// exchange + one barrier.cluster (double-buffered by iteration parity).
// Tie-break: LOWEST index (confirmed by bisection). Distance uses the LLVM
// DAGCombiner contraction order: fma(dz,dz, fma(dx,dx, dy*dy)).
// ---------------------------------------------------------------------------
__global__ void __cluster_dims__(CLUSTER, 1, 1) __launch_bounds__(THREADS, 1)
fps_kernel(const float* __restrict__ xyz)
{
    // slot = { packed(dist,idx), (y<<32|x), z } per source CTA, double buffered
    __shared__ unsigned long long slots[2][CLUSTER][3];
    __shared__ unsigned long long s_warp[NWARPS];
    __shared__ unsigned long long s_block;

    const int tid  = threadIdx.x;
    const int lane = tid & 31;
    const int warp = tid >> 5;
    const int b    = blockIdx.x / CLUSTER;   // batch
    const int rank = blockIdx.x % CLUSTER;   // cta rank within cluster

    const float* __restrict__ xb = xyz + (size_t)b * 3 * Nn;
    const float* __restrict__ yb = xb + Nn;
    const float* __restrict__ zb = xb + 2 * Nn;
    const int base = rank * PTS_CTA;

    // Register-resident point slice + running min-distance
    float px[PTS_THR], py[PTS_THR], pz[PTS_THR], dist[PTS_THR];
#pragma unroll
    for (int j = 0; j < PTS_THR; j++) {
        int gi = base + j * THREADS + tid;   // strided -> coalesced init loads
        px[j] = xb[gi];
        py[j] = yb[gi];
        pz[j] = zb[gi];
        dist[j] = 1e10f;
    }

    // Initial farthest = point 0 (reference uses fixed seed 0)
    float cx = xb[0], cy = yb[0], cz = zb[0];
    int far = 0;

    for (int i = 0; i < Mn; i++) {
        // Record the index selected *before* this update (matches lax.scan output)
        if (rank == 0 && tid == 0) g_idx[b * Mn + i] = far;

        // ---- update distances + thread-local argmax (packed u64) ----
        unsigned long long best = 0ull;
#pragma unroll
        for (int j = 0; j < PTS_THR; j++) {
            float dx = px[j] - cx;
            float dy = py[j] - cy;
            float dz = pz[j] - cz;
            // LLVM contraction of ((dx^2+dy^2)+dz^2):
            //   a1 = fma(dx,dx, dy*dy);  d = fma(dz,dz, a1)
            float d = __fmaf_rn(dz, dz, __fmaf_rn(dx, dx, __fmul_rn(dy, dy)));
            float nd = fminf(dist[j], d);
            dist[j] = nd;
            unsigned int gi = (unsigned int)(base + j * THREADS + tid);
            unsigned long long p =
                ((unsigned long long)__float_as_uint(nd) << 32) |
                (unsigned int)(~gi);                 // tie -> LOWEST index wins
            best = u64max(best, p);
        }

        // ---- warp reduce ----
        unsigned long long r = best;
#pragma unroll
        for (int off = 16; off; off >>= 1)
            r = u64max(r, __shfl_xor_sync(0xffffffffu, r, off));
        if (lane == 0) s_warp[warp] = r;
        __syncthreads();

        // ---- block reduce (warp 0 over 16 leaders) ----
        if (warp == 0) {
            unsigned long long v = (lane < NWARPS) ? s_warp[lane] : 0ull;
#pragma unroll
            for (int off = 8; off; off >>= 1)
                v = u64max(v, __shfl_xor_sync(0xffffffffu, v, off));
            if (lane == 0) s_block = v;
        }
        __syncthreads();
        unsigned long long bb = s_block;
        const int parity = i & 1;

        // ---- owner thread pushes (packed + winner xyz) to all 8 CTAs ----
        if (best == bb) {   // exactly one thread per CTA (idx is in the key)
            float wx = 0.f, wy = 0.f, wz = 0.f;
#pragma unroll
            for (int j = 0; j < PTS_THR; j++) {
                unsigned int gi = (unsigned int)(base + j * THREADS + tid);
                unsigned long long p =
                    ((unsigned long long)__float_as_uint(dist[j]) << 32) |
                    (unsigned int)(~gi);
                if (p == bb) { wx = px[j]; wy = py[j]; wz = pz[j]; }
            }
            unsigned long long xy =
                ((unsigned long long)__float_as_uint(wy) << 32) |
                (unsigned long long)__float_as_uint(wx);
            unsigned long long zz = (unsigned long long)__float_as_uint(wz);
            uint32_t laddr = smem_u32(&slots[parity][rank][0]);
#pragma unroll
            for (int c = 0; c < CLUSTER; c++) {
                uint32_t raddr;
                asm volatile("mapa.shared::cluster.u32 %0, %1, %2;"
                             : "=r"(raddr) : "r"(laddr), "r"(c));
                asm volatile("st.shared::cluster.u64 [%0], %1;"
                             :: "r"(raddr), "l"(bb) : "memory");
                asm volatile("st.shared::cluster.u64 [%0+8], %1;"
                             :: "r"(raddr), "l"(xy) : "memory");
                asm volatile("st.shared::cluster.u64 [%0+16], %1;"
                             :: "r"(raddr), "l"(zz) : "memory");
            }
        }

        // One cluster barrier per iteration (release/acquire orders the
        // DSMEM pushes; parity double-buffer makes a second barrier unneeded)
        asm volatile("barrier.cluster.arrive.aligned;" ::: "memory");
        asm volatile("barrier.cluster.wait.aligned;" ::: "memory");

        // ---- every thread picks the cluster winner from its local slots ----
        unsigned long long w = slots[parity][0][0];
        int wc = 0;
#pragma unroll
        for (int c = 1; c < CLUSTER; c++) {
            unsigned long long v = slots[parity][c][0];
            if (v > w) { w = v; wc = c; }
        }
        far = (int)(~(unsigned int)w);
        unsigned long long xy = slots[parity][wc][1];
        unsigned long long zz = slots[parity][wc][2];
        cx = __uint_as_float((unsigned int)xy);
        cy = __uint_as_float((unsigned int)(xy >> 32));
        cz = __uint_as_float((unsigned int)zz);
    }
}

// ---------------------------------------------------------------------------
// Gather epilogue: out = concat( sampled_xyz [B,3,M], sampled_feature [B,Cin,M] )
// ---------------------------------------------------------------------------
__global__ void gather_kernel(const float* __restrict__ xyz,
                              const float* __restrict__ feat,
                              float* __restrict__ out)
{
    const int P1  = Bn * 3 * Mn;
    const int TOT = P1 + Bn * CINn * Mn;
    int t = blockIdx.x * blockDim.x + threadIdx.x;
    if (t >= TOT) return;
    if (t < P1) {
        int b = t / (3 * Mn);
        int rem = t - b * 3 * Mn;
        int c = rem / Mn;
        int m = rem - c * Mn;
        int idx = g_idx[b * Mn + m];
        out[t] = xyz[(size_t)b * 3 * Nn + (size_t)c * Nn + idx];
    } else {
        int u = t - P1;
        int b = u / (CINn * Mn);
        int rem = u - b * CINn * Mn;
        int c = rem / Mn;
        int m = rem - c * Mn;
        int idx = g_idx[b * Mn + m];
        out[t] = feat[(size_t)b * CINn * Nn + (size_t)c * Nn + idx];
    }
}

extern "C" void kernel_launch(void* const* d_in, const int* in_sizes, int n_in,
                              void* d_out, int out_size)
{
    const float* xyz  = (const float*)d_in[0];  // [B,3,N]
    const float* feat = (const float*)d_in[1];  // [B,Cin,N]
    float* out = (float*)d_out;

    fps_kernel<<<Bn * CLUSTER, THREADS>>>(xyz);

    const int TOT = Bn * 3 * Mn + Bn * CINn * Mn;
    gather_kernel<<<(TOT + 255) / 256, 256>>>(xyz, feat, out);
}